// round 15
// baseline (speedup 1.0000x reference)
#include <cuda_runtime.h>
#include <cuda_fp16.h>
#include <stdint.h>
#include <math.h>

#define S_LEN 2048
#define DH 64
#define QT 128
#define KT 64
#define NTHREADS 256
#define NTILE (S_LEN / KT)
#define BH_N 32
#define MASK_ELEMS ((size_t)2 * S_LEN * S_LEN)
#define KV_ELEMS ((size_t)BH_N * S_LEN * DH)

// ---- persistent device scratch ----
__device__ uint32_t g_mask_bits[MASK_ELEMS / 32];  // 1 bit per element, 256B per q-row
__device__ __half g_Kf[KV_ELEMS];                  // K fp16 [bh][s][d]
__device__ __half g_Vt[KV_ELEMS];                  // V^T fp16 [bh][d][s]

// shared memory layout (bytes); tile rows are 144B (64 fp16 + 16B pad)
// Prologue: bytes [0, 17408) stage half the fp32 Q tile (64 rows x 272B), twice.
#define SM_K1    0
#define SM_K0    9216
#define SM_V0    18432
#define SM_V1    27648
#define SM_MSK0  36864   // mask bits [128 rows][8B]
#define SM_MSK1  37888
#define SM_TOTAL 38912

// ======================= fused prep kernel =======================
#define VT_BLOCKS 1024
#define KC_BLOCKS 4096
#define MB_BLOCKS 2048
#define PREP_BLOCKS (VT_BLOCKS + KC_BLOCKS + MB_BLOCKS)

__global__ void prep_kernel(const float* __restrict__ K, const float* __restrict__ V,
                            const void* __restrict__ M)
{
    __shared__ float Vs[64][65];
    const int bid = blockIdx.x;
    const int tid = threadIdx.x;

    if (bid < VT_BLOCKS) {
        // ---- V transpose: [bh][s][d] fp32 -> [bh][d][s] fp16 ----
        const int bh = bid >> 5, sblk = bid & 31;
        const float* src = V + ((size_t)bh * S_LEN + (size_t)sblk * 64) * DH;
        #pragma unroll
        for (int k = 0; k < 4; ++k) {
            int lin = tid + k * 256;
            int r = lin >> 4, c4 = lin & 15;
            float4 v = *(const float4*)(src + r * DH + c4 * 4);
            Vs[r][c4 * 4 + 0] = v.x; Vs[r][c4 * 4 + 1] = v.y;
            Vs[r][c4 * 4 + 2] = v.z; Vs[r][c4 * 4 + 3] = v.w;
        }
        __syncthreads();
        const int d = tid >> 2, sq = (tid & 3) * 16;
        uint32_t h[8];
        #pragma unroll
        for (int j = 0; j < 8; ++j) {
            __half2 t = __floats2half2_rn(Vs[sq + 2 * j][d], Vs[sq + 2 * j + 1][d]);
            h[j] = *(uint32_t*)&t;
        }
        size_t dst = ((size_t)bh * DH + d) * S_LEN + sblk * 64 + sq;
        *(uint4*)(g_Vt + dst)     = make_uint4(h[0], h[1], h[2], h[3]);
        *(uint4*)(g_Vt + dst + 8) = make_uint4(h[4], h[5], h[6], h[7]);
    } else if (bid < VT_BLOCKS + KC_BLOCKS) {
        // ---- K fp32 -> fp16 ----
        size_t i4 = (size_t)(bid - VT_BLOCKS) * 256 + tid;
        if (i4 < KV_ELEMS / 4) {
            float4 v = ((const float4*)K)[i4];
            __half2* H = (__half2*)g_Kf;
            H[i4 * 2]     = __floats2half2_rn(v.x, v.y);
            H[i4 * 2 + 1] = __floats2half2_rn(v.z, v.w);
        }
    } else {
        // ---- mask -> bit array; dtype mode detected per-block ----
        const unsigned char* p8 = (const unsigned char*)M;
        int loc0 = 0, loc3 = 0;
        for (int i = tid; i < 512; i += 256) {
            unsigned char v = p8[i];
            if (v) {
                if ((i & 3) == 0) loc0 = 1;
                if ((i & 3) == 3) loc3 = 1;
            }
        }
        int nz0 = __syncthreads_or(loc0);
        int nz3 = __syncthreads_or(loc3);
        const int mode = (nz0 && nz3) ? 1 : (nz0 ? 0 : 2);   // 1=uint8, 0=int32, 2=float32

        size_t i = (size_t)(bid - VT_BLOCKS - KC_BLOCKS) * 256 + tid;
        const size_t stride = (size_t)MB_BLOCKS * 256;
        for (; i < MASK_ELEMS; i += stride) {
            int nz;
            if (mode == 0)      nz = ((const int*)M)[i] != 0;
            else if (mode == 1) nz = ((const unsigned char*)M)[i] != 0;
            else                nz = ((const float*)M)[i] != 0.0f;
            unsigned wmask = __ballot_sync(0xffffffffu, nz);
            if ((tid & 31) == 0) g_mask_bits[i >> 5] = wmask;
        }
    }
}

// ======================= main kernel =======================

__device__ __forceinline__ void mma_fp16(float* c, const uint32_t* a, uint32_t b0, uint32_t b1) {
    asm volatile(
        "mma.sync.aligned.m16n8k16.row.col.f32.f16.f16.f32 "
        "{%0,%1,%2,%3}, {%4,%5,%6,%7}, {%8,%9}, {%0,%1,%2,%3};\n"
        : "+f"(c[0]), "+f"(c[1]), "+f"(c[2]), "+f"(c[3])
        : "r"(a[0]), "r"(a[1]), "r"(a[2]), "r"(a[3]), "r"(b0), "r"(b1));
}
__device__ __forceinline__ void ldsm4(uint32_t& r0, uint32_t& r1, uint32_t& r2, uint32_t& r3,
                                      uint32_t addr) {
    asm volatile("ldmatrix.sync.aligned.m8n8.x4.shared.b16 {%0,%1,%2,%3}, [%4];"
                 : "=r"(r0), "=r"(r1), "=r"(r2), "=r"(r3) : "r"(addr));
}
__device__ __forceinline__ uint32_t packh2(float a, float b) {
    __half2 t = __floats2half2_rn(a, b);
    return *(uint32_t*)&t;
}
__device__ __forceinline__ void cpa16(uint32_t dst, const void* src) {
    asm volatile("cp.async.cg.shared.global [%0], [%1], 16;\n" :: "r"(dst), "l"(src));
}
__device__ __forceinline__ void cpa8(uint32_t dst, const void* src) {
    asm volatile("cp.async.ca.shared.global [%0], [%1], 8;\n" :: "r"(dst), "l"(src));
}
__device__ __forceinline__ void cp_commit() {
    asm volatile("cp.async.commit_group;\n" ::: "memory");
}
__device__ __forceinline__ void cp_wait0() {
    asm volatile("cp.async.wait_group 0;\n" ::: "memory");
}
__device__ __forceinline__ void cp_wait1() {
    asm volatile("cp.async.wait_group 1;\n" ::: "memory");
}

__global__ void __launch_bounds__(NTHREADS, 2)
attn_kernel(const float* __restrict__ Q, float* __restrict__ Out)
{
    extern __shared__ char smem[];
    uint32_t smem_u32;
    {
        void* p = smem;
        asm("{ .reg .u64 t; cvta.to.shared.u64 t, %1; cvt.u32.u64 %0, t; }" : "=r"(smem_u32) : "l"(p));
    }

    const int tid  = threadIdx.x;
    const int w    = tid >> 5;    // 0..7
    const int lane = tid & 31;
    const int lr   = lane >> 2;   // 0..7
    const int lq   = lane & 3;    // 0..3
    const int bh   = blockIdx.y;  // 0..31
    const int b    = bh >> 4;
    const int qt   = blockIdx.x;  // 0..15

    const float* Qg = Q + ((size_t)bh * S_LEN + (size_t)qt * QT) * DH;
    const __half* KfG = g_Kf + (size_t)bh * S_LEN * DH;
    const __half* VtG = g_Vt + (size_t)bh * S_LEN * DH;  // [d][s]
    const char* MgBits = (const char*)g_mask_bits + ((size_t)b * S_LEN + (size_t)qt * QT) * 256;

    // ldmatrix per-lane B-operand selector (144B row stride -> conflict-free phases)
    const uint32_t bsel = (uint32_t)(((lane & 7) * 144) + (((lane >> 3) & 3) * 16));

    // ---- prologue: stage fp32 Q in two 64-row halves, build fragments ----
    uint32_t aQ[4][4];
    #pragma unroll
    for (int ph = 0; ph < 2; ++ph) {
        // stage rows [ph*64, ph*64+64) at [0, 17408), 272B stride
        #pragma unroll
        for (int j = 0; j < 4; ++j) {
            int c = tid + j * NTHREADS;       // 1024 chunks of 16B
            int row = c >> 4, off = (c & 15) * 16;
            cpa16(smem_u32 + row * 272 + off,
                  (const char*)(Qg + (size_t)(ph * 64 + row) * DH) + off);
        }
        cp_commit();
        cp_wait0();
        __syncthreads();
        if ((w >> 2) == ph) {   // warps 0-3 take rows 0-63, warps 4-7 rows 64-127
            const float* Qs = (const float*)smem;
            int r0 = (w & 3) * 16 + lr, r1 = r0 + 8;
            #pragma unroll
            for (int ks = 0; ks < 4; ++ks) {
                int c0 = ks * 16 + 2 * lq;
                aQ[ks][0] = packh2(Qs[r0 * 68 + c0] * 0.125f,     Qs[r0 * 68 + c0 + 1] * 0.125f);
                aQ[ks][1] = packh2(Qs[r1 * 68 + c0] * 0.125f,     Qs[r1 * 68 + c0 + 1] * 0.125f);
                aQ[ks][2] = packh2(Qs[r0 * 68 + c0 + 8] * 0.125f, Qs[r0 * 68 + c0 + 9] * 0.125f);
                aQ[ks][3] = packh2(Qs[r1 * 68 + c0 + 8] * 0.125f, Qs[r1 * 68 + c0 + 9] * 0.125f);
            }
        }
        __syncthreads();
    }

    // ---- group GA: tile 0 (K0, V0, mask0) ----
    #pragma unroll
    for (int j = 0; j < 2; ++j) {
        int c = tid + j * NTHREADS;           // 512 chunks per tile
        int row = c >> 3, off = (c & 7) * 16;
        cpa16(smem_u32 + SM_K0 + row * 144 + off, (const char*)(KfG + (size_t)row * DH) + off);
        cpa16(smem_u32 + SM_V0 + row * 144 + off, (const char*)(VtG + (size_t)row * S_LEN) + off);
    }
    if (tid < QT) cpa8(smem_u32 + SM_MSK0 + tid * 8, MgBits + (size_t)tid * 256);
    cp_commit();

    // ---- group GB: tile 1 ----
    #pragma unroll
    for (int j = 0; j < 2; ++j) {
        int c = tid + j * NTHREADS;
        int row = c >> 3, off = (c & 7) * 16;
        cpa16(smem_u32 + SM_K1 + row * 144 + off, (const char*)(KfG + (size_t)(KT + row) * DH) + off);
        cpa16(smem_u32 + SM_V1 + row * 144 + off, (const char*)(VtG + (size_t)row * S_LEN + KT) + off);
    }
    if (tid < QT) cpa8(smem_u32 + SM_MSK1 + tid * 8, MgBits + (size_t)tid * 256 + 8);
    cp_commit();

    float O[8][4];
    #pragma unroll
    for (int i = 0; i < 8; ++i)
        #pragma unroll
        for (int j = 0; j < 4; ++j) O[i][j] = 0.f;
    float l0 = 0.f, l1 = 0.f;

    #pragma unroll 2
    for (int jt = 0; jt < NTILE; ++jt) {
        const int buf = jt & 1;
        cp_wait1();          // groups complete in order: current tile's group done
        __syncthreads();     // make its copies visible to all warps

        // ---- S = (Q/8) K^T ----
        float c[8][4];
        {
            uint32_t kb = smem_u32 + (buf ? SM_K1 : SM_K0) + bsel;
            #pragma unroll
            for (int n8 = 0; n8 < 8; ++n8) {
                uint32_t b0, b1, b2, b3, b4, b5, b6, b7;
                ldsm4(b0, b1, b2, b3, kb);
                ldsm4(b4, b5, b6, b7, kb + 64);
                float* cc = c[n8];
                cc[0] = cc[1] = cc[2] = cc[3] = 0.f;
                mma_fp16(cc, aQ[0], b0, b1);
                mma_fp16(cc, aQ[1], b2, b3);
                mma_fp16(cc, aQ[2], b4, b5);
                mma_fp16(cc, aQ[3], b6, b7);
                kb += 8 * 144;
            }
        }

        // ---- mask + exp; build PV A-fragments directly in registers ----
        int q0 = w * 16 + lr;   // 0..127
        const uint32_t* mrow = (const uint32_t*)(smem + (buf ? SM_MSK1 : SM_MSK0));
        uint32_t m0a = mrow[q0 * 2],       m0b = mrow[q0 * 2 + 1];
        uint32_t m1a = mrow[(q0 + 8) * 2], m1b = mrow[(q0 + 8) * 2 + 1];
        uint32_t aP[4][4];
        float psum0 = 0.f, psum1 = 0.f;
        #pragma unroll
        for (int n8 = 0; n8 < 8; ++n8) {
            const uint32_t ma = (n8 < 4) ? m0a : m0b;
            const uint32_t mb = (n8 < 4) ? m1a : m1b;
            const int kc = (n8 & 3) * 8 + 2 * lq;
            float p0 = ((ma >> kc) & 1u)       ? 0.f : __expf(c[n8][0]);
            float p1 = ((ma >> (kc + 1)) & 1u) ? 0.f : __expf(c[n8][1]);
            float p2 = ((mb >> kc) & 1u)       ? 0.f : __expf(c[n8][2]);
            float p3 = ((mb >> (kc + 1)) & 1u) ? 0.f : __expf(c[n8][3]);
            psum0 += p0 + p1;
            psum1 += p2 + p3;
            aP[n8 >> 1][(n8 & 1) * 2 + 0] = packh2(p0, p1);
            aP[n8 >> 1][(n8 & 1) * 2 + 1] = packh2(p2, p3);
        }
        l0 += psum0;
        l1 += psum1;

        // ---- O += P V ----
        {
            uint32_t vb = smem_u32 + (buf ? SM_V1 : SM_V0) + bsel;
            #pragma unroll
            for (int n8 = 0; n8 < 8; ++n8) {
                uint32_t b0, b1, b2, b3, b4, b5, b6, b7;
                ldsm4(b0, b1, b2, b3, vb);
                ldsm4(b4, b5, b6, b7, vb + 64);
                float* oo = O[n8];
                mma_fp16(oo, aP[0], b0, b1);
                mma_fp16(oo, aP[1], b2, b3);
                mma_fp16(oo, aP[2], b4, b5);
                mma_fp16(oo, aP[3], b6, b7);
                vb += 8 * 144;
            }
        }

        // ---- all warps done with this buffer; refill it for tile jt+2 ----
        __syncthreads();
        if (jt + 2 < NTILE) {
            const int j2 = jt + 2;
            const uint32_t kdst = smem_u32 + (buf ? SM_K1 : SM_K0);
            const uint32_t vdst = smem_u32 + (buf ? SM_V1 : SM_V0);
            #pragma unroll
            for (int j = 0; j < 2; ++j) {
                int c2 = tid + j * NTHREADS;
                int row = c2 >> 3, off = (c2 & 7) * 16;
                cpa16(kdst + row * 144 + off, (const char*)(KfG + (size_t)(j2 * KT + row) * DH) + off);
                cpa16(vdst + row * 144 + off, (const char*)(VtG + (size_t)row * S_LEN + j2 * KT) + off);
            }
            if (tid < QT)
                cpa8(smem_u32 + (buf ? SM_MSK1 : SM_MSK0) + tid * 8,
                     MgBits + (size_t)tid * 256 + j2 * 8);
        }
        cp_commit();   // always commit: keeps group accounting uniform
    }

    // ---- epilogue: reduce l across lq group, normalize + store ----
    l0 += __shfl_xor_sync(0xffffffffu, l0, 1);
    l0 += __shfl_xor_sync(0xffffffffu, l0, 2);
    l1 += __shfl_xor_sync(0xffffffffu, l1, 1);
    l1 += __shfl_xor_sync(0xffffffffu, l1, 2);
    float inv0 = 1.f / l0, inv1 = 1.f / l1;
    int qrow0 = qt * QT + w * 16 + lr;
    float* Og = Out + (size_t)bh * S_LEN * DH;
    #pragma unroll
    for (int n8 = 0; n8 < 8; ++n8) {
        int dc = n8 * 8 + 2 * lq;
        float2 o0 = make_float2(O[n8][0] * inv0, O[n8][1] * inv0);
        float2 o1 = make_float2(O[n8][2] * inv1, O[n8][3] * inv1);
        *(float2*)(Og + (size_t)qrow0 * DH + dc)       = o0;
        *(float2*)(Og + (size_t)(qrow0 + 8) * DH + dc) = o1;
    }
}

extern "C" void kernel_launch(void* const* d_in, const int* in_sizes, int n_in,
                              void* d_out, int out_size)
{
    (void)in_sizes; (void)n_in; (void)out_size;
    const float* Q = (const float*)d_in[0];
    const float* K = (const float*)d_in[1];
    const float* V = (const float*)d_in[2];
    const void*  M = d_in[3];
    float* Out = (float*)d_out;

    prep_kernel<<<PREP_BLOCKS, 256>>>(K, V, M);

    cudaFuncSetAttribute(attn_kernel, cudaFuncAttributeMaxDynamicSharedMemorySize, SM_TOTAL);
    dim3 grid(S_LEN / QT, BH_N, 1);
    attn_kernel<<<grid, NTHREADS, SM_TOTAL>>>(Q, Out);
}

// round 16
// speedup vs baseline: 1.1383x; 1.1383x over previous
#include <cuda_runtime.h>
#include <cuda_fp16.h>
#include <stdint.h>
#include <math.h>

#define S_LEN 2048
#define DH 64
#define QT 64
#define KT 64
#define NTHREADS 128
#define NTILE (S_LEN / KT)
#define BH_N 32
#define MASK_ELEMS ((size_t)2 * S_LEN * S_LEN)
#define KV_ELEMS ((size_t)BH_N * S_LEN * DH)

// ---- persistent device scratch ----
__device__ uint32_t g_mask_bits[MASK_ELEMS / 32];  // 1 bit per element, 256B per q-row
__device__ __half g_Kf[KV_ELEMS];                  // K fp16 [bh][s][d]
__device__ __half g_Vt[KV_ELEMS];                  // V^T fp16 [bh][d][s]

// shared memory layout (bytes); tile rows are 144B (64 fp16 + 16B pad)
// Prologue: bytes [0, 17408) hold the fp32 Q tile (64 rows x 272B) before
// K0/K1 are first loaded. Region 0 then becomes K buffer 1.
#define SM_K1    0
#define SM_K0    9216
#define SM_V0    18432
#define SM_V1    27648
#define SM_MSK0  36864
#define SM_MSK1  37376
#define SM_TOTAL 37888

// ======================= fused prep kernel =======================
#define VT_BLOCKS 1024
#define KC_BLOCKS 4096
#define MB_BLOCKS 2048
#define PREP_BLOCKS (VT_BLOCKS + KC_BLOCKS + MB_BLOCKS)

__global__ void prep_kernel(const float* __restrict__ K, const float* __restrict__ V,
                            const void* __restrict__ M)
{
    __shared__ float Vs[64][65];
    const int bid = blockIdx.x;
    const int tid = threadIdx.x;

    if (bid < VT_BLOCKS) {
        // ---- V transpose: [bh][s][d] fp32 -> [bh][d][s] fp16 ----
        const int bh = bid >> 5, sblk = bid & 31;
        const float* src = V + ((size_t)bh * S_LEN + (size_t)sblk * 64) * DH;
        #pragma unroll
        for (int k = 0; k < 4; ++k) {
            int lin = tid + k * 256;
            int r = lin >> 4, c4 = lin & 15;
            float4 v = *(const float4*)(src + r * DH + c4 * 4);
            Vs[r][c4 * 4 + 0] = v.x; Vs[r][c4 * 4 + 1] = v.y;
            Vs[r][c4 * 4 + 2] = v.z; Vs[r][c4 * 4 + 3] = v.w;
        }
        __syncthreads();
        const int d = tid >> 2, sq = (tid & 3) * 16;
        uint32_t h[8];
        #pragma unroll
        for (int j = 0; j < 8; ++j) {
            __half2 t = __floats2half2_rn(Vs[sq + 2 * j][d], Vs[sq + 2 * j + 1][d]);
            h[j] = *(uint32_t*)&t;
        }
        size_t dst = ((size_t)bh * DH + d) * S_LEN + sblk * 64 + sq;
        *(uint4*)(g_Vt + dst)     = make_uint4(h[0], h[1], h[2], h[3]);
        *(uint4*)(g_Vt + dst + 8) = make_uint4(h[4], h[5], h[6], h[7]);
    } else if (bid < VT_BLOCKS + KC_BLOCKS) {
        // ---- K fp32 -> fp16 ----
        size_t i4 = (size_t)(bid - VT_BLOCKS) * 256 + tid;
        if (i4 < KV_ELEMS / 4) {
            float4 v = ((const float4*)K)[i4];
            __half2* H = (__half2*)g_Kf;
            H[i4 * 2]     = __floats2half2_rn(v.x, v.y);
            H[i4 * 2 + 1] = __floats2half2_rn(v.z, v.w);
        }
    } else {
        // ---- mask -> bit array; dtype mode detected per-block ----
        const unsigned char* p8 = (const unsigned char*)M;
        int loc0 = 0, loc3 = 0;
        for (int i = tid; i < 512; i += 256) {
            unsigned char v = p8[i];
            if (v) {
                if ((i & 3) == 0) loc0 = 1;
                if ((i & 3) == 3) loc3 = 1;
            }
        }
        int nz0 = __syncthreads_or(loc0);
        int nz3 = __syncthreads_or(loc3);
        const int mode = (nz0 && nz3) ? 1 : (nz0 ? 0 : 2);   // 1=uint8, 0=int32, 2=float32

        // 4 strided sub-blocks of 32 elements per iteration: lane l handles
        // element base + 32k + l, so ballot bit order matches element order.
        const int lane = tid & 31;
        size_t base = ((size_t)(bid - VT_BLOCKS - KC_BLOCKS) * 256 + (tid & ~31)) * 4;
        const size_t stride = (size_t)MB_BLOCKS * 1024;
        for (; base < MASK_ELEMS; base += stride) {
            #pragma unroll
            for (int k = 0; k < 4; ++k) {
                size_t i = base + 32 * k + lane;
                int nz;
                if (mode == 0)      nz = ((const int*)M)[i] != 0;
                else if (mode == 1) nz = ((const unsigned char*)M)[i] != 0;
                else                nz = ((const float*)M)[i] != 0.0f;
                unsigned wmask = __ballot_sync(0xffffffffu, nz);
                if (lane == 0) g_mask_bits[i >> 5] = wmask;
            }
        }
    }
}

// ======================= main kernel =======================

__device__ __forceinline__ void mma_fp16(float* c, const uint32_t* a, uint32_t b0, uint32_t b1) {
    asm volatile(
        "mma.sync.aligned.m16n8k16.row.col.f32.f16.f16.f32 "
        "{%0,%1,%2,%3}, {%4,%5,%6,%7}, {%8,%9}, {%0,%1,%2,%3};\n"
        : "+f"(c[0]), "+f"(c[1]), "+f"(c[2]), "+f"(c[3])
        : "r"(a[0]), "r"(a[1]), "r"(a[2]), "r"(a[3]), "r"(b0), "r"(b1));
}
__device__ __forceinline__ void ldsm4(uint32_t& r0, uint32_t& r1, uint32_t& r2, uint32_t& r3,
                                      uint32_t addr) {
    asm volatile("ldmatrix.sync.aligned.m8n8.x4.shared.b16 {%0,%1,%2,%3}, [%4];"
                 : "=r"(r0), "=r"(r1), "=r"(r2), "=r"(r3) : "r"(addr));
}
__device__ __forceinline__ uint32_t packh2(float a, float b) {
    __half2 t = __floats2half2_rn(a, b);
    return *(uint32_t*)&t;
}
__device__ __forceinline__ void cpa16(uint32_t dst, const void* src) {
    asm volatile("cp.async.cg.shared.global [%0], [%1], 16;\n" :: "r"(dst), "l"(src));
}
__device__ __forceinline__ void cpa8(uint32_t dst, const void* src) {
    asm volatile("cp.async.ca.shared.global [%0], [%1], 8;\n" :: "r"(dst), "l"(src));
}
__device__ __forceinline__ void cp_commit() {
    asm volatile("cp.async.commit_group;\n" ::: "memory");
}
__device__ __forceinline__ void cp_wait0() {
    asm volatile("cp.async.wait_group 0;\n" ::: "memory");
}
__device__ __forceinline__ void cp_wait1() {
    asm volatile("cp.async.wait_group 1;\n" ::: "memory");
}

__global__ void __launch_bounds__(NTHREADS, 4)
attn_kernel(const float* __restrict__ Q, float* __restrict__ Out)
{
    extern __shared__ char smem[];
    uint32_t smem_u32;
    {
        void* p = smem;
        asm("{ .reg .u64 t; cvta.to.shared.u64 t, %1; cvt.u32.u64 %0, t; }" : "=r"(smem_u32) : "l"(p));
    }

    const int tid  = threadIdx.x;
    const int w    = tid >> 5;    // 0..3
    const int lane = tid & 31;
    const int lr   = lane >> 2;   // 0..7
    const int lq   = lane & 3;    // 0..3
    const int bh   = blockIdx.y;  // 0..31
    const int b    = bh >> 4;
    const int qt   = blockIdx.x;  // 0..31

    const float* Qg = Q + ((size_t)bh * S_LEN + (size_t)qt * QT) * DH;
    const __half* KfG = g_Kf + (size_t)bh * S_LEN * DH;
    const __half* VtG = g_Vt + (size_t)bh * S_LEN * DH;  // [d][s]
    const char* MgBits = (const char*)g_mask_bits + ((size_t)b * S_LEN + (size_t)qt * QT) * 256;

    // ldmatrix per-lane B-operand selector (144B row stride -> conflict-free phases)
    const uint32_t bsel = (uint32_t)(((lane & 7) * 144) + (((lane >> 3) & 3) * 16));

    // ---- prologue A: stage this CTA's fp32 Q tile (64 x 256B, 272B stride) ----
    #pragma unroll
    for (int j = 0; j < 8; ++j) {
        int c = tid + j * NTHREADS;       // 1024 chunks of 16B
        int row = c >> 4, off = (c & 15) * 16;
        cpa16(smem_u32 + row * 272 + off, (const char*)(Qg + (size_t)row * DH) + off);
    }
    cp_commit();
    cp_wait0();
    __syncthreads();

    // ---- convert Q to A-fragments in registers (scale 0.125 folded) ----
    uint32_t aQ[4][4];
    {
        const float* Qs = (const float*)smem;
        int r0 = w * 16 + lr, r1 = r0 + 8;
        #pragma unroll
        for (int ks = 0; ks < 4; ++ks) {
            int c0 = ks * 16 + 2 * lq;
            aQ[ks][0] = packh2(Qs[r0 * 68 + c0] * 0.125f,     Qs[r0 * 68 + c0 + 1] * 0.125f);
            aQ[ks][1] = packh2(Qs[r1 * 68 + c0] * 0.125f,     Qs[r1 * 68 + c0 + 1] * 0.125f);
            aQ[ks][2] = packh2(Qs[r0 * 68 + c0 + 8] * 0.125f, Qs[r0 * 68 + c0 + 9] * 0.125f);
            aQ[ks][3] = packh2(Qs[r1 * 68 + c0 + 8] * 0.125f, Qs[r1 * 68 + c0 + 9] * 0.125f);
        }
    }
    __syncthreads();   // Q staging done; regions now free for K buffers

    // ---- group GA: tile 0 (K0, V0, mask0) ----
    #pragma unroll
    for (int j = 0; j < 4; ++j) {
        int c = tid + j * NTHREADS;
        int row = c >> 3, off = (c & 7) * 16;
        cpa16(smem_u32 + SM_K0 + row * 144 + off, (const char*)(KfG + (size_t)row * DH) + off);
        cpa16(smem_u32 + SM_V0 + row * 144 + off, (const char*)(VtG + (size_t)row * S_LEN) + off);
    }
    if (tid < QT) cpa8(smem_u32 + SM_MSK0 + tid * 8, MgBits + (size_t)tid * 256);
    cp_commit();

    // ---- group GB: tile 1 (K1 into region 0, V1, mask1) ----
    #pragma unroll
    for (int j = 0; j < 4; ++j) {
        int c = tid + j * NTHREADS;
        int row = c >> 3, off = (c & 7) * 16;
        cpa16(smem_u32 + SM_K1 + row * 144 + off, (const char*)(KfG + (size_t)(KT + row) * DH) + off);
        cpa16(smem_u32 + SM_V1 + row * 144 + off, (const char*)(VtG + (size_t)row * S_LEN + KT) + off);
    }
    if (tid < QT) cpa8(smem_u32 + SM_MSK1 + tid * 8, MgBits + (size_t)tid * 256 + 8);
    cp_commit();

    float O[8][4];
    #pragma unroll
    for (int i = 0; i < 8; ++i)
        #pragma unroll
        for (int j = 0; j < 4; ++j) O[i][j] = 0.f;
    float l0 = 0.f, l1 = 0.f;

    for (int jt = 0; jt < NTILE; ++jt) {
        const int buf = jt & 1;
        cp_wait1();          // groups complete in order: current tile's group done
        __syncthreads();     // make its copies visible to all warps

        // ---- S = (Q/8) K^T ----
        float c[8][4];
        {
            uint32_t kb = smem_u32 + (buf ? SM_K1 : SM_K0) + bsel;
            #pragma unroll
            for (int n8 = 0; n8 < 8; ++n8) {
                uint32_t b0, b1, b2, b3, b4, b5, b6, b7;
                ldsm4(b0, b1, b2, b3, kb);
                ldsm4(b4, b5, b6, b7, kb + 64);
                float* cc = c[n8];
                cc[0] = cc[1] = cc[2] = cc[3] = 0.f;
                mma_fp16(cc, aQ[0], b0, b1);
                mma_fp16(cc, aQ[1], b2, b3);
                mma_fp16(cc, aQ[2], b4, b5);
                mma_fp16(cc, aQ[3], b6, b7);
                kb += 8 * 144;
            }
        }

        // ---- mask + exp; build PV A-fragments DIRECTLY in registers ----
        int q0 = w * 16 + lr;
        const uint32_t* mrow = (const uint32_t*)(smem + (buf ? SM_MSK1 : SM_MSK0));
        uint32_t m0a = mrow[q0 * 2],       m0b = mrow[q0 * 2 + 1];
        uint32_t m1a = mrow[(q0 + 8) * 2], m1b = mrow[(q0 + 8) * 2 + 1];
        uint32_t aP[4][4];
        float psum0 = 0.f, psum1 = 0.f;
        #pragma unroll
        for (int n8 = 0; n8 < 8; ++n8) {
            const uint32_t ma = (n8 < 4) ? m0a : m0b;
            const uint32_t mb = (n8 < 4) ? m1a : m1b;
            const int kc = (n8 & 3) * 8 + 2 * lq;
            float p0 = ((ma >> kc) & 1u)       ? 0.f : __expf(c[n8][0]);
            float p1 = ((ma >> (kc + 1)) & 1u) ? 0.f : __expf(c[n8][1]);
            float p2 = ((mb >> kc) & 1u)       ? 0.f : __expf(c[n8][2]);
            float p3 = ((mb >> (kc + 1)) & 1u) ? 0.f : __expf(c[n8][3]);
            psum0 += p0 + p1;
            psum1 += p2 + p3;
            aP[n8 >> 1][(n8 & 1) * 2 + 0] = packh2(p0, p1);
            aP[n8 >> 1][(n8 & 1) * 2 + 1] = packh2(p2, p3);
        }
        l0 += psum0;
        l1 += psum1;

        // ---- O += P V ----
        {
            uint32_t vb = smem_u32 + (buf ? SM_V1 : SM_V0) + bsel;
            #pragma unroll
            for (int n8 = 0; n8 < 8; ++n8) {
                uint32_t b0, b1, b2, b3, b4, b5, b6, b7;
                ldsm4(b0, b1, b2, b3, vb);
                ldsm4(b4, b5, b6, b7, vb + 64);
                float* oo = O[n8];
                mma_fp16(oo, aP[0], b0, b1);
                mma_fp16(oo, aP[1], b2, b3);
                mma_fp16(oo, aP[2], b4, b5);
                mma_fp16(oo, aP[3], b6, b7);
                vb += 8 * 144;
            }
        }

        // ---- all warps done with this buffer; refill it for tile jt+2 ----
        __syncthreads();
        if (jt + 2 < NTILE) {
            const int j2 = jt + 2;
            const uint32_t kdst = smem_u32 + (buf ? SM_K1 : SM_K0);
            const uint32_t vdst = smem_u32 + (buf ? SM_V1 : SM_V0);
            #pragma unroll
            for (int j = 0; j < 4; ++j) {
                int c2 = tid + j * NTHREADS;
                int row = c2 >> 3, off = (c2 & 7) * 16;
                cpa16(kdst + row * 144 + off, (const char*)(KfG + (size_t)(j2 * KT + row) * DH) + off);
                cpa16(vdst + row * 144 + off, (const char*)(VtG + (size_t)row * S_LEN + j2 * KT) + off);
            }
            if (tid < QT)
                cpa8(smem_u32 + (buf ? SM_MSK1 : SM_MSK0) + tid * 8,
                     MgBits + (size_t)tid * 256 + j2 * 8);
        }
        cp_commit();   // always commit: keeps group accounting uniform
    }

    // ---- epilogue: reduce l across lq group, normalize + store ----
    l0 += __shfl_xor_sync(0xffffffffu, l0, 1);
    l0 += __shfl_xor_sync(0xffffffffu, l0, 2);
    l1 += __shfl_xor_sync(0xffffffffu, l1, 1);
    l1 += __shfl_xor_sync(0xffffffffu, l1, 2);
    float inv0 = 1.f / l0, inv1 = 1.f / l1;
    int qrow0 = qt * QT + w * 16 + lr;
    float* Og = Out + (size_t)bh * S_LEN * DH;
    #pragma unroll
    for (int n8 = 0; n8 < 8; ++n8) {
        int dc = n8 * 8 + 2 * lq;
        float2 o0 = make_float2(O[n8][0] * inv0, O[n8][1] * inv0);
        float2 o1 = make_float2(O[n8][2] * inv1, O[n8][3] * inv1);
        *(float2*)(Og + (size_t)qrow0 * DH + dc)       = o0;
        *(float2*)(Og + (size_t)(qrow0 + 8) * DH + dc) = o1;
    }
}

extern "C" void kernel_launch(void* const* d_in, const int* in_sizes, int n_in,
                              void* d_out, int out_size)
{
    (void)in_sizes; (void)n_in; (void)out_size;
    const float* Q = (const float*)d_in[0];
    const float* K = (const float*)d_in[1];
    const float* V = (const float*)d_in[2];
    const void*  M = d_in[3];
    float* Out = (float*)d_out;

    prep_kernel<<<PREP_BLOCKS, 256>>>(K, V, M);

    cudaFuncSetAttribute(attn_kernel, cudaFuncAttributeMaxDynamicSharedMemorySize, SM_TOTAL);
    dim3 grid(S_LEN / QT, BH_N, 1);
    attn_kernel<<<grid, NTHREADS, SM_TOTAL>>>(Q, Out);
}

// round 17
// speedup vs baseline: 1.1478x; 1.0083x over previous
#include <cuda_runtime.h>
#include <cuda_fp16.h>
#include <stdint.h>
#include <math.h>

#define S_LEN 2048
#define DH 64
#define QT 64
#define KT 64
#define NTHREADS 128
#define NTILE (S_LEN / KT)
#define BH_N 32
#define MASK_ELEMS ((size_t)2 * S_LEN * S_LEN)
#define KV_ELEMS ((size_t)BH_N * S_LEN * DH)

// ---- persistent device scratch ----
__device__ uint32_t g_mask_bits[MASK_ELEMS / 32];  // 1 bit per element, 256B per q-row
__device__ __half g_Kf[KV_ELEMS];                  // K fp16 [bh][s][d]
__device__ __half g_Vt[KV_ELEMS];                  // V^T fp16 [bh][d][s]

// shared memory layout (bytes); tile rows are 144B (64 fp16 + 16B pad)
// Prologue: bytes [0, 17408) hold the fp32 Q tile (64 rows x 272B) before
// K0/K1 are first loaded. Region 0 then becomes K buffer 1.
#define SM_K1    0
#define SM_K0    9216
#define SM_V0    18432
#define SM_V1    27648
#define SM_MSK0  36864
#define SM_MSK1  37376
#define SM_TOTAL 37888

// ======================= fused prep kernel =======================
// Block ranges (mask FIRST -- it is the largest traffic stream):
//   [0, 8192)                maskbits: exactly 1024 elements per block, one pass
//   [8192, 8192+1024)        vtrans   (bh = r>>5, sblk = r&31)
//   [9216, 9216+4096)        K conv
#define MB_BLOCKS 8192
#define VT_BLOCKS 1024
#define KC_BLOCKS 4096
#define PREP_BLOCKS (MB_BLOCKS + VT_BLOCKS + KC_BLOCKS)

__global__ void prep_kernel(const float* __restrict__ K, const float* __restrict__ V,
                            const void* __restrict__ M)
{
    __shared__ float Vs[64][65];
    const int bid = blockIdx.x;
    const int tid = threadIdx.x;

    if (bid < MB_BLOCKS) {
        // ---- mask -> bit array; dtype mode detected per-block ----
        const unsigned char* p8 = (const unsigned char*)M;
        int loc0 = 0, loc3 = 0;
        for (int i = tid; i < 512; i += 256) {
            unsigned char v = p8[i];
            if (v) {
                if ((i & 3) == 0) loc0 = 1;
                if ((i & 3) == 3) loc3 = 1;
            }
        }
        int nz0 = __syncthreads_or(loc0);
        int nz3 = __syncthreads_or(loc3);
        const int mode = (nz0 && nz3) ? 1 : (nz0 ? 0 : 2);   // 1=uint8, 0=int32, 2=float32

        // one pass: 8 warps x 4 groups x 32 lanes = 1024 elements per block
        const int warp = tid >> 5, lane = tid & 31;
        const size_t base = (size_t)bid * 1024 + (size_t)warp * 128;
        #pragma unroll
        for (int k = 0; k < 4; ++k) {
            size_t i = base + 32 * k + lane;
            int nz;
            if (mode == 0)      nz = ((const int*)M)[i] != 0;
            else if (mode == 1) nz = ((const unsigned char*)M)[i] != 0;
            else                nz = ((const float*)M)[i] != 0.0f;
            unsigned wmask = __ballot_sync(0xffffffffu, nz);
            if (lane == 0) g_mask_bits[i >> 5] = wmask;
        }
    } else if (bid < MB_BLOCKS + VT_BLOCKS) {
        // ---- V transpose: [bh][s][d] fp32 -> [bh][d][s] fp16 ----
        const int r = bid - MB_BLOCKS;
        const int bh = r >> 5, sblk = r & 31;
        const float* src = V + ((size_t)bh * S_LEN + (size_t)sblk * 64) * DH;
        #pragma unroll
        for (int k = 0; k < 4; ++k) {
            int lin = tid + k * 256;
            int rr = lin >> 4, c4 = lin & 15;
            float4 v = *(const float4*)(src + rr * DH + c4 * 4);
            Vs[rr][c4 * 4 + 0] = v.x; Vs[rr][c4 * 4 + 1] = v.y;
            Vs[rr][c4 * 4 + 2] = v.z; Vs[rr][c4 * 4 + 3] = v.w;
        }
        __syncthreads();
        const int d = tid >> 2, sq = (tid & 3) * 16;
        uint32_t h[8];
        #pragma unroll
        for (int j = 0; j < 8; ++j) {
            __half2 t = __floats2half2_rn(Vs[sq + 2 * j][d], Vs[sq + 2 * j + 1][d]);
            h[j] = *(uint32_t*)&t;
        }
        size_t dst = ((size_t)bh * DH + d) * S_LEN + sblk * 64 + sq;
        *(uint4*)(g_Vt + dst)     = make_uint4(h[0], h[1], h[2], h[3]);
        *(uint4*)(g_Vt + dst + 8) = make_uint4(h[4], h[5], h[6], h[7]);
    } else {
        // ---- K fp32 -> fp16 ----
        size_t i4 = (size_t)(bid - MB_BLOCKS - VT_BLOCKS) * 256 + tid;
        if (i4 < KV_ELEMS / 4) {
            float4 v = ((const float4*)K)[i4];
            __half2* H = (__half2*)g_Kf;
            H[i4 * 2]     = __floats2half2_rn(v.x, v.y);
            H[i4 * 2 + 1] = __floats2half2_rn(v.z, v.w);
        }
    }
}

// ======================= main kernel =======================

__device__ __forceinline__ void mma_fp16(float* c, const uint32_t* a, uint32_t b0, uint32_t b1) {
    asm volatile(
        "mma.sync.aligned.m16n8k16.row.col.f32.f16.f16.f32 "
        "{%0,%1,%2,%3}, {%4,%5,%6,%7}, {%8,%9}, {%0,%1,%2,%3};\n"
        : "+f"(c[0]), "+f"(c[1]), "+f"(c[2]), "+f"(c[3])
        : "r"(a[0]), "r"(a[1]), "r"(a[2]), "r"(a[3]), "r"(b0), "r"(b1));
}
__device__ __forceinline__ void ldsm4(uint32_t& r0, uint32_t& r1, uint32_t& r2, uint32_t& r3,
                                      uint32_t addr) {
    asm volatile("ldmatrix.sync.aligned.m8n8.x4.shared.b16 {%0,%1,%2,%3}, [%4];"
                 : "=r"(r0), "=r"(r1), "=r"(r2), "=r"(r3) : "r"(addr));
}
__device__ __forceinline__ uint32_t packh2(float a, float b) {
    __half2 t = __floats2half2_rn(a, b);
    return *(uint32_t*)&t;
}
__device__ __forceinline__ void cpa16(uint32_t dst, const void* src) {
    asm volatile("cp.async.cg.shared.global [%0], [%1], 16;\n" :: "r"(dst), "l"(src));
}
__device__ __forceinline__ void cpa8(uint32_t dst, const void* src) {
    asm volatile("cp.async.ca.shared.global [%0], [%1], 8;\n" :: "r"(dst), "l"(src));
}
__device__ __forceinline__ void cp_commit() {
    asm volatile("cp.async.commit_group;\n" ::: "memory");
}
__device__ __forceinline__ void cp_wait0() {
    asm volatile("cp.async.wait_group 0;\n" ::: "memory");
}
__device__ __forceinline__ void cp_wait1() {
    asm volatile("cp.async.wait_group 1;\n" ::: "memory");
}

__global__ void __launch_bounds__(NTHREADS, 4)
attn_kernel(const float* __restrict__ Q, float* __restrict__ Out)
{
    extern __shared__ char smem[];
    uint32_t smem_u32;
    {
        void* p = smem;
        asm("{ .reg .u64 t; cvta.to.shared.u64 t, %1; cvt.u32.u64 %0, t; }" : "=r"(smem_u32) : "l"(p));
    }

    const int tid  = threadIdx.x;
    const int w    = tid >> 5;    // 0..3
    const int lane = tid & 31;
    const int lr   = lane >> 2;   // 0..7
    const int lq   = lane & 3;    // 0..3
    const int bh   = blockIdx.y;  // 0..31
    const int b    = bh >> 4;
    const int qt   = blockIdx.x;  // 0..31

    const float* Qg = Q + ((size_t)bh * S_LEN + (size_t)qt * QT) * DH;
    const __half* KfG = g_Kf + (size_t)bh * S_LEN * DH;
    const __half* VtG = g_Vt + (size_t)bh * S_LEN * DH;  // [d][s]
    const char* MgBits = (const char*)g_mask_bits + ((size_t)b * S_LEN + (size_t)qt * QT) * 256;

    // ldmatrix per-lane B-operand selector (144B row stride -> conflict-free phases)
    const uint32_t bsel = (uint32_t)(((lane & 7) * 144) + (((lane >> 3) & 3) * 16));

    // ---- prologue A: stage this CTA's fp32 Q tile (64 x 256B, 272B stride) ----
    #pragma unroll
    for (int j = 0; j < 8; ++j) {
        int c = tid + j * NTHREADS;       // 1024 chunks of 16B
        int row = c >> 4, off = (c & 15) * 16;
        cpa16(smem_u32 + row * 272 + off, (const char*)(Qg + (size_t)row * DH) + off);
    }
    cp_commit();
    cp_wait0();
    __syncthreads();

    // ---- convert Q to A-fragments in registers (scale 0.125 folded) ----
    uint32_t aQ[4][4];
    {
        const float* Qs = (const float*)smem;
        int r0 = w * 16 + lr, r1 = r0 + 8;
        #pragma unroll
        for (int ks = 0; ks < 4; ++ks) {
            int c0 = ks * 16 + 2 * lq;
            aQ[ks][0] = packh2(Qs[r0 * 68 + c0] * 0.125f,     Qs[r0 * 68 + c0 + 1] * 0.125f);
            aQ[ks][1] = packh2(Qs[r1 * 68 + c0] * 0.125f,     Qs[r1 * 68 + c0 + 1] * 0.125f);
            aQ[ks][2] = packh2(Qs[r0 * 68 + c0 + 8] * 0.125f, Qs[r0 * 68 + c0 + 9] * 0.125f);
            aQ[ks][3] = packh2(Qs[r1 * 68 + c0 + 8] * 0.125f, Qs[r1 * 68 + c0 + 9] * 0.125f);
        }
    }
    __syncthreads();   // Q staging done; regions now free for K buffers

    // ---- group GA: tile 0 (K0, V0, mask0) ----
    #pragma unroll
    for (int j = 0; j < 4; ++j) {
        int c = tid + j * NTHREADS;
        int row = c >> 3, off = (c & 7) * 16;
        cpa16(smem_u32 + SM_K0 + row * 144 + off, (const char*)(KfG + (size_t)row * DH) + off);
        cpa16(smem_u32 + SM_V0 + row * 144 + off, (const char*)(VtG + (size_t)row * S_LEN) + off);
    }
    if (tid < QT) cpa8(smem_u32 + SM_MSK0 + tid * 8, MgBits + (size_t)tid * 256);
    cp_commit();

    // ---- group GB: tile 1 (K1 into region 0, V1, mask1) ----
    #pragma unroll
    for (int j = 0; j < 4; ++j) {
        int c = tid + j * NTHREADS;
        int row = c >> 3, off = (c & 7) * 16;
        cpa16(smem_u32 + SM_K1 + row * 144 + off, (const char*)(KfG + (size_t)(KT + row) * DH) + off);
        cpa16(smem_u32 + SM_V1 + row * 144 + off, (const char*)(VtG + (size_t)row * S_LEN + KT) + off);
    }
    if (tid < QT) cpa8(smem_u32 + SM_MSK1 + tid * 8, MgBits + (size_t)tid * 256 + 8);
    cp_commit();

    float O[8][4];
    #pragma unroll
    for (int i = 0; i < 8; ++i)
        #pragma unroll
        for (int j = 0; j < 4; ++j) O[i][j] = 0.f;
    float l0 = 0.f, l1 = 0.f;

    for (int jt = 0; jt < NTILE; ++jt) {
        const int buf = jt & 1;
        cp_wait1();          // groups complete in order: current tile's group done
        __syncthreads();     // make its copies visible to all warps

        // ---- S = (Q/8) K^T ----
        float c[8][4];
        {
            uint32_t kb = smem_u32 + (buf ? SM_K1 : SM_K0) + bsel;
            #pragma unroll
            for (int n8 = 0; n8 < 8; ++n8) {
                uint32_t b0, b1, b2, b3, b4, b5, b6, b7;
                ldsm4(b0, b1, b2, b3, kb);
                ldsm4(b4, b5, b6, b7, kb + 64);
                float* cc = c[n8];
                cc[0] = cc[1] = cc[2] = cc[3] = 0.f;
                mma_fp16(cc, aQ[0], b0, b1);
                mma_fp16(cc, aQ[1], b2, b3);
                mma_fp16(cc, aQ[2], b4, b5);
                mma_fp16(cc, aQ[3], b6, b7);
                kb += 8 * 144;
            }
        }

        // ---- mask + exp; build PV A-fragments DIRECTLY in registers ----
        int q0 = w * 16 + lr;
        const uint32_t* mrow = (const uint32_t*)(smem + (buf ? SM_MSK1 : SM_MSK0));
        uint32_t m0a = mrow[q0 * 2],       m0b = mrow[q0 * 2 + 1];
        uint32_t m1a = mrow[(q0 + 8) * 2], m1b = mrow[(q0 + 8) * 2 + 1];
        uint32_t aP[4][4];
        float psum0 = 0.f, psum1 = 0.f;
        #pragma unroll
        for (int n8 = 0; n8 < 8; ++n8) {
            const uint32_t ma = (n8 < 4) ? m0a : m0b;
            const uint32_t mb = (n8 < 4) ? m1a : m1b;
            const int kc = (n8 & 3) * 8 + 2 * lq;
            float p0 = ((ma >> kc) & 1u)       ? 0.f : __expf(c[n8][0]);
            float p1 = ((ma >> (kc + 1)) & 1u) ? 0.f : __expf(c[n8][1]);
            float p2 = ((mb >> kc) & 1u)       ? 0.f : __expf(c[n8][2]);
            float p3 = ((mb >> (kc + 1)) & 1u) ? 0.f : __expf(c[n8][3]);
            psum0 += p0 + p1;
            psum1 += p2 + p3;
            aP[n8 >> 1][(n8 & 1) * 2 + 0] = packh2(p0, p1);
            aP[n8 >> 1][(n8 & 1) * 2 + 1] = packh2(p2, p3);
        }
        l0 += psum0;
        l1 += psum1;

        // ---- O += P V ----
        {
            uint32_t vb = smem_u32 + (buf ? SM_V1 : SM_V0) + bsel;
            #pragma unroll
            for (int n8 = 0; n8 < 8; ++n8) {
                uint32_t b0, b1, b2, b3, b4, b5, b6, b7;
                ldsm4(b0, b1, b2, b3, vb);
                ldsm4(b4, b5, b6, b7, vb + 64);
                float* oo = O[n8];
                mma_fp16(oo, aP[0], b0, b1);
                mma_fp16(oo, aP[1], b2, b3);
                mma_fp16(oo, aP[2], b4, b5);
                mma_fp16(oo, aP[3], b6, b7);
                vb += 8 * 144;
            }
        }

        // ---- all warps done with this buffer; refill it for tile jt+2 ----
        __syncthreads();
        if (jt + 2 < NTILE) {
            const int j2 = jt + 2;
            const uint32_t kdst = smem_u32 + (buf ? SM_K1 : SM_K0);
            const uint32_t vdst = smem_u32 + (buf ? SM_V1 : SM_V0);
            #pragma unroll
            for (int j = 0; j < 4; ++j) {
                int c2 = tid + j * NTHREADS;
                int row = c2 >> 3, off = (c2 & 7) * 16;
                cpa16(kdst + row * 144 + off, (const char*)(KfG + (size_t)(j2 * KT + row) * DH) + off);
                cpa16(vdst + row * 144 + off, (const char*)(VtG + (size_t)row * S_LEN + j2 * KT) + off);
            }
            if (tid < QT)
                cpa8(smem_u32 + (buf ? SM_MSK1 : SM_MSK0) + tid * 8,
                     MgBits + (size_t)tid * 256 + j2 * 8);
        }
        cp_commit();   // always commit: keeps group accounting uniform
    }

    // ---- epilogue: reduce l across lq group, normalize + store ----
    l0 += __shfl_xor_sync(0xffffffffu, l0, 1);
    l0 += __shfl_xor_sync(0xffffffffu, l0, 2);
    l1 += __shfl_xor_sync(0xffffffffu, l1, 1);
    l1 += __shfl_xor_sync(0xffffffffu, l1, 2);
    float inv0 = 1.f / l0, inv1 = 1.f / l1;
    int qrow0 = qt * QT + w * 16 + lr;
    float* Og = Out + (size_t)bh * S_LEN * DH;
    #pragma unroll
    for (int n8 = 0; n8 < 8; ++n8) {
        int dc = n8 * 8 + 2 * lq;
        float2 o0 = make_float2(O[n8][0] * inv0, O[n8][1] * inv0);
        float2 o1 = make_float2(O[n8][2] * inv1, O[n8][3] * inv1);
        *(float2*)(Og + (size_t)qrow0 * DH + dc)       = o0;
        *(float2*)(Og + (size_t)(qrow0 + 8) * DH + dc) = o1;
    }
}

extern "C" void kernel_launch(void* const* d_in, const int* in_sizes, int n_in,
                              void* d_out, int out_size)
{
    (void)in_sizes; (void)n_in; (void)out_size;
    const float* Q = (const float*)d_in[0];
    const float* K = (const float*)d_in[1];
    const float* V = (const float*)d_in[2];
    const void*  M = d_in[3];
    float* Out = (float*)d_out;

    prep_kernel<<<PREP_BLOCKS, 256>>>(K, V, M);

    cudaFuncSetAttribute(attn_kernel, cudaFuncAttributeMaxDynamicSharedMemorySize, SM_TOTAL);
    dim3 grid(S_LEN / QT, BH_N, 1);
    attn_kernel<<<grid, NTHREADS, SM_TOTAL>>>(Q, Out);
}